// round 2
// baseline (speedup 1.0000x reference)
#include <cuda_runtime.h>

#define Bn 64
#define Mn 200
#define Sn 50
#define Qn 20
#define Dn 128
#define Vn 50000
#define HOPSn 3
#define NEG_INF -1e9f

// Scratch (static __device__ globals: allowed; no runtime allocation)
__device__ float g_emb[4][Bn * Mn][Dn];   // embeddings of A0, C0, C1, C2  (~26 MB)
__device__ float g_u[Bn][Dn];             // controller state after hops
__device__ int   g_nonpad[Bn * Mn];       // mem_nonpad mask

// ---------------------------------------------------------------------------
// Kernel 1: story embedding gather for all 4 tables.
// One block per (b,m). 4 warps; warp g gathers table g. Lane covers 4 d's
// (float4). PE[s,d] = a_s + b_s * c_d  (rank-2 decomposition).
// ---------------------------------------------------------------------------
__global__ void __launch_bounds__(128) embed_story_kernel(
    const int* __restrict__ story,
    const float* __restrict__ T0, const float* __restrict__ T1,
    const float* __restrict__ T2, const float* __restrict__ T3)
{
    __shared__ int   idx[Sn];
    __shared__ float wa[Sn], wb[Sn];
    const int bm = blockIdx.x;
    const int t  = threadIdx.x;

    if (t < Sn) {
        int w = story[bm * Sn + t];
        idx[t] = w;
        float j = (float)(t + 1);
        wa[t] = 1.0f - j * (1.0f / Sn);
        wb[t] = 2.0f * j * (1.0f / Sn) - 1.0f;
    }
    __syncthreads();
    int np = __syncthreads_or((t < Sn) && (idx[t] != 0));
    if (t == 0) g_nonpad[bm] = np;

    const int grp  = t >> 5;
    const int lane = t & 31;
    const float4* tab = (const float4*)(grp == 0 ? T0 : grp == 1 ? T1
                                        : grp == 2 ? T2 : T3);
    const float cx = (float)(4 * lane + 1) * (1.0f / Dn);
    const float cy = (float)(4 * lane + 2) * (1.0f / Dn);
    const float cz = (float)(4 * lane + 3) * (1.0f / Dn);
    const float cw = (float)(4 * lane + 4) * (1.0f / Dn);

    float4 acc = make_float4(0.f, 0.f, 0.f, 0.f);
#pragma unroll
    for (int s = 0; s < Sn; s++) {
        int   w = idx[s];
        float a = wa[s], b = wb[s];
        float4 r = tab[w * (Dn / 4) + lane];
        acc.x = fmaf(fmaf(b, cx, a), r.x, acc.x);
        acc.y = fmaf(fmaf(b, cy, a), r.y, acc.y);
        acc.z = fmaf(fmaf(b, cz, a), r.z, acc.z);
        acc.w = fmaf(fmaf(b, cw, a), r.w, acc.w);
    }
    ((float4*)g_emb[grp][bm])[lane] = acc;
}

// ---------------------------------------------------------------------------
// Kernel 2: query embed (fused prologue) + 3 hops. One block per batch b.
// A_tabs = emb[0..2], C_tabs = emb[1..3] (adjacent weight tying).
// ---------------------------------------------------------------------------
__global__ void __launch_bounds__(128) hops_kernel(
    const int* __restrict__ question, const float* __restrict__ Bemb,
    const float* __restrict__ TA, const float* __restrict__ TC)
{
    __shared__ float u_sh[Dn];
    __shared__ float sc[Mn];
    __shared__ float red[4];
    __shared__ float s_max, s_sum;
    __shared__ int   qidx[Qn];
    __shared__ float qa[Qn], qb[Qn];
    const int b    = blockIdx.x;
    const int t    = threadIdx.x;
    const int warp = t >> 5;
    const int lane = t & 31;

    // ---- query embedding u^1 (fused; thread = d) ----
    if (t < Qn) {
        int w = question[b * Qn + t];
        qidx[t] = w;
        float j = (float)(t + 1);
        qa[t] = 1.0f - j * (1.0f / Qn);
        qb[t] = 2.0f * j * (1.0f / Qn) - 1.0f;
    }
    __syncthreads();
    {
        const float cd = (float)(t + 1) * (1.0f / Dn);
        float acc = 0.f;
#pragma unroll
        for (int q = 0; q < Qn; q++) {
            float wgt = fmaf(qb[q], cd, qa[q]);
            acc = fmaf(wgt, Bemb[qidx[q] * Dn + t], acc);
        }
        u_sh[t] = acc;
    }
    __syncthreads();

    for (int k = 0; k < HOPSn; k++) {
        const float4* embA = (const float4*)g_emb[k];
        const float*  embC = (const float*)g_emb[k + 1];

        // ---- scores[m] = (m_k + TA) . u ----
        float4 uu = ((const float4*)u_sh)[lane];
        for (int m = warp; m < Mn; m += 4) {
            float4 e  = embA[(b * Mn + m) * (Dn / 4) + lane];
            float4 ta = ((const float4*)TA)[m * (Dn / 4) + lane];
            float p = (e.x + ta.x) * uu.x + (e.y + ta.y) * uu.y
                    + (e.z + ta.z) * uu.z + (e.w + ta.w) * uu.w;
#pragma unroll
            for (int off = 16; off; off >>= 1)
                p += __shfl_down_sync(0xffffffffu, p, off);
            if (lane == 0) sc[m] = g_nonpad[b * Mn + m] ? p : NEG_INF;
        }
        __syncthreads();

        // ---- softmax over M ----
        float lm = -3e38f;
        for (int m = t; m < Mn; m += 128) lm = fmaxf(lm, sc[m]);
#pragma unroll
        for (int off = 16; off; off >>= 1)
            lm = fmaxf(lm, __shfl_down_sync(0xffffffffu, lm, off));
        if (lane == 0) red[warp] = lm;
        __syncthreads();
        if (t == 0)
            s_max = fmaxf(fmaxf(red[0], red[1]), fmaxf(red[2], red[3]));
        __syncthreads();
        const float mm = s_max;
        float ls = 0.f;
        for (int m = t; m < Mn; m += 128) {
            float e = __expf(sc[m] - mm);
            sc[m] = e;
            ls += e;
        }
#pragma unroll
        for (int off = 16; off; off >>= 1)
            ls += __shfl_down_sync(0xffffffffu, ls, off);
        if (lane == 0) red[warp] = ls;
        __syncthreads();
        if (t == 0) s_sum = red[0] + red[1] + red[2] + red[3];
        __syncthreads();
        const float inv = 1.0f / s_sum;

        // ---- o[d] = sum_m p[m] * (c_k[m,d] + TC[m,d]) ; thread = d ----
        float o = 0.f;
#pragma unroll 4
        for (int m = 0; m < Mn; m++) {
            float c = embC[(b * Mn + m) * Dn + t] + TC[m * Dn + t];
            o = fmaf(sc[m], c, o);
        }
        __syncthreads();
        u_sh[t] += o * inv;
        __syncthreads();
    }
    g_u[b][t] = u_sh[t];
}

// ---------------------------------------------------------------------------
// Kernel 3: logits = u @ W^T + bias. Thread = one vocab row v, all 64 batch
// accumulators in registers; u broadcast-read from SMEM (conflict-free).
// ---------------------------------------------------------------------------
__global__ void __launch_bounds__(128) logits_kernel(
    const float* __restrict__ W, const float* __restrict__ bias,
    float* __restrict__ out)
{
    __shared__ float4 u_sh[Bn * (Dn / 4)];   // 32 KB
    const int t = threadIdx.x;
    const float4* gu4 = (const float4*)g_u;
#pragma unroll
    for (int i = 0; i < (Bn * Dn / 4) / 128; i++)
        u_sh[t + i * 128] = gu4[t + i * 128];
    __syncthreads();

    const int v = blockIdx.x * 128 + t;
    if (v >= Vn) return;

    const float4* Wv = (const float4*)(W + (size_t)v * Dn);
    float acc[Bn];
#pragma unroll
    for (int b = 0; b < Bn; b++) acc[b] = 0.f;

#pragma unroll 1
    for (int d4 = 0; d4 < Dn / 4; d4++) {
        float4 w4 = Wv[d4];
#pragma unroll
        for (int b = 0; b < Bn; b++) {
            float4 uu = u_sh[b * (Dn / 4) + d4];   // broadcast across warp
            acc[b] = fmaf(w4.x, uu.x, acc[b]);
            acc[b] = fmaf(w4.y, uu.y, acc[b]);
            acc[b] = fmaf(w4.z, uu.z, acc[b]);
            acc[b] = fmaf(w4.w, uu.w, acc[b]);
        }
    }
    const float bv = bias[v];
#pragma unroll
    for (int b = 0; b < Bn; b++)
        out[(size_t)b * Vn + v] = acc[b] + bv;
}

// ---------------------------------------------------------------------------
extern "C" void kernel_launch(void* const* d_in, const int* in_sizes, int n_in,
                              void* d_out, int out_size)
{
    const int*   story    = (const int*)d_in[0];
    const int*   question = (const int*)d_in[1];
    const float* A0       = (const float*)d_in[2];
    const float* C0       = (const float*)d_in[3];
    const float* C1       = (const float*)d_in[4];
    const float* C2       = (const float*)d_in[5];
    const float* Bemb     = (const float*)d_in[6];
    const float* TA       = (const float*)d_in[7];
    const float* TC       = (const float*)d_in[8];
    const float* W        = (const float*)d_in[9];
    const float* bias     = (const float*)d_in[10];
    float* out = (float*)d_out;

    embed_story_kernel<<<Bn * Mn, 128>>>(story, A0, C0, C1, C2);
    hops_kernel<<<Bn, 128>>>(question, Bemb, TA, TC);
    logits_kernel<<<(Vn + 127) / 128, 128>>>(W, bias, out);
}

// round 3
// speedup vs baseline: 1.6998x; 1.6998x over previous
#include <cuda_runtime.h>

#define Bn 64
#define Mn 200
#define Sn 50
#define Qn 20
#define Dn 128
#define Vn 50000
#define HOPSn 3
#define NEG_INF -1e9f

// Scratch (static __device__ globals: allowed; no runtime allocation)
__device__ float g_emb[4][Bn * Mn][Dn];   // embeddings of A0, C0, C1, C2  (~26 MB)
__device__ float g_u[Bn][Dn];             // controller state after hops
__device__ int   g_nonpad[Bn * Mn];       // mem_nonpad mask

// ---------------------------------------------------------------------------
// Kernel 1: story embedding gather for all 4 tables. (unchanged from R2 pass)
// One block per (b,m). 4 warps; warp g gathers table g. Lane covers 4 d's
// (float4). PE[s,d] = a_s + b_s * c_d  (rank-2 decomposition).
// ---------------------------------------------------------------------------
__global__ void __launch_bounds__(128) embed_story_kernel(
    const int* __restrict__ story,
    const float* __restrict__ T0, const float* __restrict__ T1,
    const float* __restrict__ T2, const float* __restrict__ T3)
{
    __shared__ int   idx[Sn];
    __shared__ float wa[Sn], wb[Sn];
    const int bm = blockIdx.x;
    const int t  = threadIdx.x;

    if (t < Sn) {
        int w = story[bm * Sn + t];
        idx[t] = w;
        float j = (float)(t + 1);
        wa[t] = 1.0f - j * (1.0f / Sn);
        wb[t] = 2.0f * j * (1.0f / Sn) - 1.0f;
    }
    __syncthreads();
    int np = __syncthreads_or((t < Sn) && (idx[t] != 0));
    if (t == 0) g_nonpad[bm] = np;

    const int grp  = t >> 5;
    const int lane = t & 31;
    const float4* tab = (const float4*)(grp == 0 ? T0 : grp == 1 ? T1
                                        : grp == 2 ? T2 : T3);
    const float cx = (float)(4 * lane + 1) * (1.0f / Dn);
    const float cy = (float)(4 * lane + 2) * (1.0f / Dn);
    const float cz = (float)(4 * lane + 3) * (1.0f / Dn);
    const float cw = (float)(4 * lane + 4) * (1.0f / Dn);

    float4 acc = make_float4(0.f, 0.f, 0.f, 0.f);
#pragma unroll
    for (int s = 0; s < Sn; s++) {
        int   w = idx[s];
        float a = wa[s], b = wb[s];
        float4 r = tab[w * (Dn / 4) + lane];
        acc.x = fmaf(fmaf(b, cx, a), r.x, acc.x);
        acc.y = fmaf(fmaf(b, cy, a), r.y, acc.y);
        acc.z = fmaf(fmaf(b, cz, a), r.z, acc.z);
        acc.w = fmaf(fmaf(b, cw, a), r.w, acc.w);
    }
    ((float4*)g_emb[grp][bm])[lane] = acc;
}

// ---------------------------------------------------------------------------
// Kernel 2: query embed + 3 hops, REBUILT with 1024 threads per batch b.
//  - scores: 32 warps, each covers ~6-7 memories
//  - softmax: 1 element/thread, two-level reduction
//  - o: 8 groups x 128 threads partition M (25 m's each), smem reduce
// ---------------------------------------------------------------------------
__global__ void __launch_bounds__(1024) hops_kernel(
    const int* __restrict__ question, const float* __restrict__ Bemb,
    const float* __restrict__ TA, const float* __restrict__ TC)
{
    __shared__ float u_sh[Dn];
    __shared__ float sc[Mn];
    __shared__ float partial[8][Dn];
    __shared__ float red[32];
    __shared__ float s_max, s_sum;
    __shared__ int   qidx[Qn];
    __shared__ float qa[Qn], qb[Qn];

    const int b    = blockIdx.x;
    const int t    = threadIdx.x;
    const int warp = t >> 5;
    const int lane = t & 31;

    // ---- query embedding u^1 (threads 0..127, thread = d) ----
    if (t < Qn) {
        int w = question[b * Qn + t];
        qidx[t] = w;
        float j = (float)(t + 1);
        qa[t] = 1.0f - j * (1.0f / Qn);
        qb[t] = 2.0f * j * (1.0f / Qn) - 1.0f;
    }
    __syncthreads();
    if (t < Dn) {
        const float cd = (float)(t + 1) * (1.0f / Dn);
        float acc = 0.f;
#pragma unroll
        for (int q = 0; q < Qn; q++) {
            float wgt = fmaf(qb[q], cd, qa[q]);
            acc = fmaf(wgt, Bemb[qidx[q] * Dn + t], acc);
        }
        u_sh[t] = acc;
    }
    __syncthreads();

    for (int k = 0; k < HOPSn; k++) {
        const float4* embA = (const float4*)g_emb[k];
        const float*  embC = (const float*)g_emb[k + 1];

        // ---- scores[m] = (m_k + TA) . u : warp per memory, 32 warps ----
        float4 uu = ((const float4*)u_sh)[lane];
        for (int m = warp; m < Mn; m += 32) {
            float4 e  = embA[(b * Mn + m) * (Dn / 4) + lane];
            float4 ta = ((const float4*)TA)[m * (Dn / 4) + lane];
            float p = (e.x + ta.x) * uu.x + (e.y + ta.y) * uu.y
                    + (e.z + ta.z) * uu.z + (e.w + ta.w) * uu.w;
#pragma unroll
            for (int off = 16; off; off >>= 1)
                p += __shfl_down_sync(0xffffffffu, p, off);
            if (lane == 0) sc[m] = g_nonpad[b * Mn + m] ? p : NEG_INF;
        }
        __syncthreads();

        // ---- softmax over M=200: one element per thread ----
        float lm = (t < Mn) ? sc[t] : -3e38f;
#pragma unroll
        for (int off = 16; off; off >>= 1)
            lm = fmaxf(lm, __shfl_down_sync(0xffffffffu, lm, off));
        if (lane == 0) red[warp] = lm;
        __syncthreads();
        if (warp == 0) {
            float v = red[lane];
#pragma unroll
            for (int off = 16; off; off >>= 1)
                v = fmaxf(v, __shfl_down_sync(0xffffffffu, v, off));
            if (lane == 0) s_max = v;
        }
        __syncthreads();
        float e = 0.f;
        if (t < Mn) {
            e = __expf(sc[t] - s_max);
            sc[t] = e;
        }
#pragma unroll
        for (int off = 16; off; off >>= 1)
            e += __shfl_down_sync(0xffffffffu, e, off);
        if (lane == 0) red[warp] = e;
        __syncthreads();
        if (warp == 0) {
            float v = red[lane];
#pragma unroll
            for (int off = 16; off; off >>= 1)
                v += __shfl_down_sync(0xffffffffu, v, off);
            if (lane == 0) s_sum = v;
        }
        __syncthreads();
        const float inv = 1.0f / s_sum;

        // ---- o[d] = sum_m p[m]*(c_k[m,d]+TC[m,d]) : 8 groups x 128 ----
        const int g = t >> 7;     // group 0..7
        const int d = t & 127;    // dim
        float o = 0.f;
#pragma unroll
        for (int mi = 0; mi < Mn / 8; mi++) {
            int m = g + mi * 8;
            float c = embC[(b * Mn + m) * Dn + d] + TC[m * Dn + d];
            o = fmaf(sc[m], c, o);
        }
        partial[g][d] = o;
        __syncthreads();
        if (t < Dn) {
            float s = 0.f;
#pragma unroll
            for (int g2 = 0; g2 < 8; g2++) s += partial[g2][t];
            u_sh[t] += s * inv;
        }
        __syncthreads();
    }
    if (t < Dn) g_u[b][t] = u_sh[t];
}

// ---------------------------------------------------------------------------
// Kernel 3: logits = u @ W^T + bias. (unchanged from R2 pass)
// ---------------------------------------------------------------------------
__global__ void __launch_bounds__(128) logits_kernel(
    const float* __restrict__ W, const float* __restrict__ bias,
    float* __restrict__ out)
{
    __shared__ float4 u_sh[Bn * (Dn / 4)];   // 32 KB
    const int t = threadIdx.x;
    const float4* gu4 = (const float4*)g_u;
#pragma unroll
    for (int i = 0; i < (Bn * Dn / 4) / 128; i++)
        u_sh[t + i * 128] = gu4[t + i * 128];
    __syncthreads();

    const int v = blockIdx.x * 128 + t;
    if (v >= Vn) return;

    const float4* Wv = (const float4*)(W + (size_t)v * Dn);
    float acc[Bn];
#pragma unroll
    for (int b = 0; b < Bn; b++) acc[b] = 0.f;

#pragma unroll 1
    for (int d4 = 0; d4 < Dn / 4; d4++) {
        float4 w4 = Wv[d4];
#pragma unroll
        for (int b = 0; b < Bn; b++) {
            float4 uu = u_sh[b * (Dn / 4) + d4];   // broadcast across warp
            acc[b] = fmaf(w4.x, uu.x, acc[b]);
            acc[b] = fmaf(w4.y, uu.y, acc[b]);
            acc[b] = fmaf(w4.z, uu.z, acc[b]);
            acc[b] = fmaf(w4.w, uu.w, acc[b]);
        }
    }
    const float bv = bias[v];
#pragma unroll
    for (int b = 0; b < Bn; b++)
        out[(size_t)b * Vn + v] = acc[b] + bv;
}

// ---------------------------------------------------------------------------
extern "C" void kernel_launch(void* const* d_in, const int* in_sizes, int n_in,
                              void* d_out, int out_size)
{
    const int*   story    = (const int*)d_in[0];
    const int*   question = (const int*)d_in[1];
    const float* A0       = (const float*)d_in[2];
    const float* C0       = (const float*)d_in[3];
    const float* C1       = (const float*)d_in[4];
    const float* C2       = (const float*)d_in[5];
    const float* Bemb     = (const float*)d_in[6];
    const float* TA       = (const float*)d_in[7];
    const float* TC       = (const float*)d_in[8];
    const float* W        = (const float*)d_in[9];
    const float* bias     = (const float*)d_in[10];
    float* out = (float*)d_out;

    embed_story_kernel<<<Bn * Mn, 128>>>(story, A0, C0, C1, C2);
    hops_kernel<<<Bn, 1024>>>(question, Bemb, TA, TC);
    logits_kernel<<<(Vn + 127) / 128, 128>>>(W, bias, out);
}

// round 4
// speedup vs baseline: 1.7846x; 1.0499x over previous
#include <cuda_runtime.h>

#define Bn 64
#define Mn 200
#define Sn 50
#define Qn 20
#define Dn 128
#define Vn 50000
#define HOPSn 3
#define NEG_INF -1e9f

// Scratch (static __device__ globals: allowed; no runtime allocation)
__device__ float g_emb[4][Bn * Mn][Dn];   // embeddings of A0, C0, C1, C2  (~26 MB)
__device__ float g_u[Bn][Dn];             // controller state after hops
__device__ int   g_nonpad[Bn * Mn];       // mem_nonpad mask

// ---------------------------------------------------------------------------
// Kernel 1: story embedding gather, REBUILT.
//  grid = (Bn*Mn, 4): blockIdx.y selects the table -> x-fastest rasterization
//  makes each table a scheduling phase, so the active working set is ONE
//  25.6MB table (L2-resident) instead of all four (thrash).
//  4 warps split the 50 rows (12-13 each) with explicit batch-4 loads (MLP>=4
//  per warp); per-warp float4 partials combined through smem.
// ---------------------------------------------------------------------------
__device__ __forceinline__ void pe_fma(float4& acc, const float4& r, int s,
                                       float cx, float cy, float cz, float cw)
{
    float j = (float)(s + 1);
    float a = 1.0f - j * (1.0f / Sn);
    float bb = 2.0f * j * (1.0f / Sn) - 1.0f;
    acc.x = fmaf(fmaf(bb, cx, a), r.x, acc.x);
    acc.y = fmaf(fmaf(bb, cy, a), r.y, acc.y);
    acc.z = fmaf(fmaf(bb, cz, a), r.z, acc.z);
    acc.w = fmaf(fmaf(bb, cw, a), r.w, acc.w);
}

__global__ void __launch_bounds__(128) embed_story_kernel(
    const int* __restrict__ story,
    const float* __restrict__ T0, const float* __restrict__ T1,
    const float* __restrict__ T2, const float* __restrict__ T3)
{
    __shared__ int    idx[Sn];
    __shared__ float4 part[4][32];
    const int bm   = blockIdx.x;
    const int tb   = blockIdx.y;
    const int t    = threadIdx.x;
    const int warp = t >> 5;
    const int lane = t & 31;

    if (t < Sn) idx[t] = story[bm * Sn + t];
    __syncthreads();
    if (tb == 0) {
        int np = __syncthreads_or((t < Sn) && (idx[t] != 0));
        if (t == 0) g_nonpad[bm] = np;
    }

    const float4* tab = (const float4*)(tb == 0 ? T0 : tb == 1 ? T1
                                        : tb == 2 ? T2 : T3);
    const float cx = (float)(4 * lane + 1) * (1.0f / Dn);
    const float cy = (float)(4 * lane + 2) * (1.0f / Dn);
    const float cz = (float)(4 * lane + 3) * (1.0f / Dn);
    const float cw = (float)(4 * lane + 4) * (1.0f / Dn);

    float4 acc = make_float4(0.f, 0.f, 0.f, 0.f);
    const int start = (Sn * warp) >> 2;        // {0,12,25,37}
    const int end   = (Sn * (warp + 1)) >> 2;  // {12,25,37,50}
    int s = start;
    for (; s + 4 <= end; s += 4) {
        int w0 = idx[s], w1 = idx[s + 1], w2 = idx[s + 2], w3 = idx[s + 3];
        float4 r0 = tab[w0 * (Dn / 4) + lane];
        float4 r1 = tab[w1 * (Dn / 4) + lane];
        float4 r2 = tab[w2 * (Dn / 4) + lane];
        float4 r3 = tab[w3 * (Dn / 4) + lane];
        pe_fma(acc, r0, s,     cx, cy, cz, cw);
        pe_fma(acc, r1, s + 1, cx, cy, cz, cw);
        pe_fma(acc, r2, s + 2, cx, cy, cz, cw);
        pe_fma(acc, r3, s + 3, cx, cy, cz, cw);
    }
    for (; s < end; s++) {
        float4 r = tab[idx[s] * (Dn / 4) + lane];
        pe_fma(acc, r, s, cx, cy, cz, cw);
    }
    part[warp][lane] = acc;
    __syncthreads();
    if (warp == 0) {
        float4 a0 = part[0][lane], a1 = part[1][lane];
        float4 a2 = part[2][lane], a3 = part[3][lane];
        float4 r;
        r.x = (a0.x + a1.x) + (a2.x + a3.x);
        r.y = (a0.y + a1.y) + (a2.y + a3.y);
        r.z = (a0.z + a1.z) + (a2.z + a3.z);
        r.w = (a0.w + a1.w) + (a2.w + a3.w);
        ((float4*)g_emb[tb][bm])[lane] = r;
    }
}

// ---------------------------------------------------------------------------
// Kernel 2: query embed + 3 hops, 1024 threads per batch b.
//  Score phase v2: per-lane partials -> padded smem transpose -> 200-thread
//  reduction (kills the 5-deep shfl chain per memory).
// ---------------------------------------------------------------------------
__global__ void __launch_bounds__(1024) hops_kernel(
    const int* __restrict__ question, const float* __restrict__ Bemb,
    const float* __restrict__ TA, const float* __restrict__ TC)
{
    __shared__ float u_sh[Dn];
    __shared__ float sc[Mn];
    __shared__ float scp[Mn][33];        // padded: conflict-free transpose
    __shared__ float partial[8][Dn];
    __shared__ float red[32];
    __shared__ float s_max, s_sum;
    __shared__ int   qidx[Qn];
    __shared__ float qa[Qn], qb[Qn];

    const int b    = blockIdx.x;
    const int t    = threadIdx.x;
    const int warp = t >> 5;
    const int lane = t & 31;

    // ---- query embedding u^1 ----
    if (t < Qn) {
        int w = question[b * Qn + t];
        qidx[t] = w;
        float j = (float)(t + 1);
        qa[t] = 1.0f - j * (1.0f / Qn);
        qb[t] = 2.0f * j * (1.0f / Qn) - 1.0f;
    }
    __syncthreads();
    if (t < Dn) {
        const float cd = (float)(t + 1) * (1.0f / Dn);
        float acc = 0.f;
#pragma unroll
        for (int q = 0; q < Qn; q++) {
            float wgt = fmaf(qb[q], cd, qa[q]);
            acc = fmaf(wgt, Bemb[qidx[q] * Dn + t], acc);
        }
        u_sh[t] = acc;
    }
    __syncthreads();

    for (int k = 0; k < HOPSn; k++) {
        const float4* embA = (const float4*)g_emb[k];
        const float*  embC = (const float*)g_emb[k + 1];

        // ---- per-lane score partials (no shfl): warp covers m stride 32 ----
        float4 uu = ((const float4*)u_sh)[lane];
#pragma unroll 2
        for (int m = warp; m < Mn; m += 32) {
            float4 e  = embA[(b * Mn + m) * (Dn / 4) + lane];
            float4 ta = ((const float4*)TA)[m * (Dn / 4) + lane];
            float p = (e.x + ta.x) * uu.x + (e.y + ta.y) * uu.y
                    + (e.z + ta.z) * uu.z + (e.w + ta.w) * uu.w;
            scp[m][lane] = p;
        }
        __syncthreads();

        // ---- reduce 32 partials per m (4-way split accumulators) ----
        float lm = -3e38f;
        if (t < Mn) {
            float p0 = 0.f, p1 = 0.f, p2 = 0.f, p3 = 0.f;
#pragma unroll
            for (int i = 0; i < 32; i += 4) {
                p0 += scp[t][i];
                p1 += scp[t][i + 1];
                p2 += scp[t][i + 2];
                p3 += scp[t][i + 3];
            }
            float p = (p0 + p1) + (p2 + p3);
            p = g_nonpad[b * Mn + t] ? p : NEG_INF;
            sc[t] = p;
            lm = p;
        }
        // ---- softmax max ----
#pragma unroll
        for (int off = 16; off; off >>= 1)
            lm = fmaxf(lm, __shfl_down_sync(0xffffffffu, lm, off));
        if (lane == 0) red[warp] = lm;
        __syncthreads();
        if (warp == 0) {
            float v = red[lane];
#pragma unroll
            for (int off = 16; off; off >>= 1)
                v = fmaxf(v, __shfl_down_sync(0xffffffffu, v, off));
            if (lane == 0) s_max = v;
        }
        __syncthreads();
        // ---- exp + sum ----
        float e = 0.f;
        if (t < Mn) {
            e = __expf(sc[t] - s_max);
            sc[t] = e;
        }
#pragma unroll
        for (int off = 16; off; off >>= 1)
            e += __shfl_down_sync(0xffffffffu, e, off);
        if (lane == 0) red[warp] = e;
        __syncthreads();
        if (warp == 0) {
            float v = red[lane];
#pragma unroll
            for (int off = 16; off; off >>= 1)
                v += __shfl_down_sync(0xffffffffu, v, off);
            if (lane == 0) s_sum = v;
        }
        __syncthreads();
        const float inv = 1.0f / s_sum;

        // ---- o[d] = sum_m p[m]*(c_k[m,d]+TC[m,d]) : 8 groups x 128 ----
        const int g = t >> 7;     // group 0..7
        const int d = t & 127;    // dim
        float o = 0.f;
#pragma unroll
        for (int mi = 0; mi < Mn / 8; mi++) {
            int m = g + mi * 8;
            float c = embC[(b * Mn + m) * Dn + d] + TC[m * Dn + d];
            o = fmaf(sc[m], c, o);
        }
        partial[g][d] = o;
        __syncthreads();
        if (t < Dn) {
            float s2 = 0.f;
#pragma unroll
            for (int g2 = 0; g2 < 8; g2++) s2 += partial[g2][t];
            u_sh[t] += s2 * inv;
        }
        __syncthreads();
    }
    if (t < Dn) g_u[b][t] = u_sh[t];
}

// ---------------------------------------------------------------------------
// Kernel 3: logits = u @ W^T + bias. (unchanged)
// ---------------------------------------------------------------------------
__global__ void __launch_bounds__(128) logits_kernel(
    const float* __restrict__ W, const float* __restrict__ bias,
    float* __restrict__ out)
{
    __shared__ float4 u_sh[Bn * (Dn / 4)];   // 32 KB
    const int t = threadIdx.x;
    const float4* gu4 = (const float4*)g_u;
#pragma unroll
    for (int i = 0; i < (Bn * Dn / 4) / 128; i++)
        u_sh[t + i * 128] = gu4[t + i * 128];
    __syncthreads();

    const int v = blockIdx.x * 128 + t;
    if (v >= Vn) return;

    const float4* Wv = (const float4*)(W + (size_t)v * Dn);
    float acc[Bn];
#pragma unroll
    for (int b = 0; b < Bn; b++) acc[b] = 0.f;

#pragma unroll 1
    for (int d4 = 0; d4 < Dn / 4; d4++) {
        float4 w4 = Wv[d4];
#pragma unroll
        for (int b = 0; b < Bn; b++) {
            float4 uu = u_sh[b * (Dn / 4) + d4];   // broadcast across warp
            acc[b] = fmaf(w4.x, uu.x, acc[b]);
            acc[b] = fmaf(w4.y, uu.y, acc[b]);
            acc[b] = fmaf(w4.z, uu.z, acc[b]);
            acc[b] = fmaf(w4.w, uu.w, acc[b]);
        }
    }
    const float bv = bias[v];
#pragma unroll
    for (int b = 0; b < Bn; b++)
        out[(size_t)b * Vn + v] = acc[b] + bv;
}

// ---------------------------------------------------------------------------
extern "C" void kernel_launch(void* const* d_in, const int* in_sizes, int n_in,
                              void* d_out, int out_size)
{
    const int*   story    = (const int*)d_in[0];
    const int*   question = (const int*)d_in[1];
    const float* A0       = (const float*)d_in[2];
    const float* C0       = (const float*)d_in[3];
    const float* C1       = (const float*)d_in[4];
    const float* C2       = (const float*)d_in[5];
    const float* Bemb     = (const float*)d_in[6];
    const float* TA       = (const float*)d_in[7];
    const float* TC       = (const float*)d_in[8];
    const float* W        = (const float*)d_in[9];
    const float* bias     = (const float*)d_in[10];
    float* out = (float*)d_out;

    embed_story_kernel<<<dim3(Bn * Mn, 4), 128>>>(story, A0, C0, C1, C2);
    hops_kernel<<<Bn, 1024>>>(question, Bemb, TA, TC);
    logits_kernel<<<(Vn + 127) / 128, 128>>>(W, bias, out);
}